// round 13
// baseline (speedup 1.0000x reference)
#include <cuda_runtime.h>
#include <cuda_bf16.h>
#include <math.h>

// Problem constants (fixed by setup_inputs)
#define T_TOK   8192      // B*S = 4*2048
#define DDIM    1024
#define NEXP    8
#define HDIM    1024
#define NSLOT   (2*T_TOK) // top-2 slots

// ---------------- scratch (no allocations allowed) ----------------
__device__ int   g_counts[NEXP];
__device__ int   g_offsets[NEXP];
__device__ int   g_slot_e[NSLOT];
__device__ int   g_slot_pos[NSLOT];
__device__ float g_slot_g[NSLOT];
__device__ int   g_tok[NSLOT];
__device__ float g_gate[NSLOT];

// ---------------- packed fp32x2 helpers (Blackwell FFMA2) ----------------
__device__ __forceinline__ unsigned long long pack2(float x, float y) {
    unsigned long long r;
    asm("mov.b64 %0, {%1, %2};" : "=l"(r) : "f"(x), "f"(y));
    return r;
}
__device__ __forceinline__ void fma2(unsigned long long& d,
                                     unsigned long long a,
                                     unsigned long long b) {
    asm("fma.rn.f32x2 %0, %1, %2, %0;" : "+l"(d) : "l"(a), "l"(b));
}
union F2 { unsigned long long u; float f[2]; };

// ---------------- kernel 0: zero expert counters ----------------
__global__ void moe_zero_counts() {
    if (threadIdx.x < NEXP) g_counts[threadIdx.x] = 0;
}

// ---------------- kernel 1: gating (one warp per token) ----------------
// logits[e] = x[t]·Wg[:,e]; top-2 of logits; renormalized top-2 softmax
// gates == exp(l_i)/(exp(l0)+exp(l1)) (identical to softmax-then-renorm).
__global__ void moe_gate(const float* __restrict__ x,
                         const float* __restrict__ Wg) {
    __shared__ float sWgT[NEXP][DDIM];   // 32 KB, transposed for conflict-free reads
    int tid = threadIdx.x;
    for (int i = tid; i < DDIM * NEXP; i += 256) {
        // Wg is [D, E] row-major: element i -> d = i/8, e = i%8
        sWgT[i & 7][i >> 3] = Wg[i];
    }
    __syncthreads();

    int warp = tid >> 5;
    int lane = tid & 31;
    int t = blockIdx.x * 8 + warp;          // grid = 1024 blocks * 8 warps = 8192

    float acc[NEXP];
#pragma unroll
    for (int e = 0; e < NEXP; e++) acc[e] = 0.f;

    const float* xr = x + (size_t)t * DDIM;
    for (int d = lane; d < DDIM; d += 32) {
        float xv = xr[d];
#pragma unroll
        for (int e = 0; e < NEXP; e++) acc[e] += xv * sWgT[e][d];
    }
#pragma unroll
    for (int e = 0; e < NEXP; e++) {
#pragma unroll
        for (int o = 16; o > 0; o >>= 1)
            acc[e] += __shfl_xor_sync(0xFFFFFFFFu, acc[e], o);
    }

    if (lane == 0) {
        int e0 = 0; float m1 = acc[0];
#pragma unroll
        for (int e = 1; e < NEXP; e++)
            if (acc[e] > m1) { m1 = acc[e]; e0 = e; }
        int e1 = (e0 == 0) ? 1 : 0; float m2 = acc[e1];
#pragma unroll
        for (int e = 0; e < NEXP; e++)
            if (e != e0 && acc[e] > m2) { m2 = acc[e]; e1 = e; }
        float r  = expf(m2 - m1);           // <= 1
        float g0 = 1.f / (1.f + r);
        float g1 = r   / (1.f + r);

        int p0 = atomicAdd(&g_counts[e0], 1);
        int p1 = atomicAdd(&g_counts[e1], 1);
        int s = 2 * t;
        g_slot_e[s]     = e0; g_slot_pos[s]     = p0; g_slot_g[s]     = g0;
        g_slot_e[s + 1] = e1; g_slot_pos[s + 1] = p1; g_slot_g[s + 1] = g1;
    }
}

// ---------------- kernel 2: tiny prefix over 8 experts ----------------
__global__ void moe_offsets() {
    if (threadIdx.x == 0) {
        int s = 0;
#pragma unroll
        for (int e = 0; e < NEXP; e++) { g_offsets[e] = s; s += g_counts[e]; }
    }
}

// ---------------- kernel 3: scatter token lists ----------------
__global__ void moe_scatter() {
    int i = blockIdx.x * 256 + threadIdx.x;     // NSLOT = 16384 threads
    if (i < NSLOT) {
        int e   = g_slot_e[i];
        int loc = g_offsets[e] + g_slot_pos[i];
        g_tok[loc]  = i >> 1;                   // token id
        g_gate[loc] = g_slot_g[i];
    }
}

// ---------------- kernel 4: zero output (out gets 2 atomic adds/elem) ----
__global__ void moe_zero_out(float4* __restrict__ out4) {
    int gid = blockIdx.x * 256 + threadIdx.x;   // out_size/4 threads
    out4[gid] = make_float4(0.f, 0.f, 0.f, 0.f);
}

// ---------------- kernel 5: grouped gather-SGEMM, 128x128x8 tile ----------
// Y[row, h] = gate(row) * ( x[tok(row)] · We[e][:, h] + be[e][h] )
// accumulated into out[tok(row), h] via atomicAdd (exactly 2 adds/elem ->
// commutative -> deterministic).
__global__ void __launch_bounds__(256, 2)
moe_gemm(const float* __restrict__ x,
         const float* __restrict__ We,
         const float* __restrict__ be,
         float* __restrict__ out) {
    const int e    = blockIdx.z;
    const int rows = g_counts[e];
    const int m0   = blockIdx.y * 128;
    if (m0 >= rows) return;
    const int base = g_offsets[e];
    const int n0   = blockIdx.x * 128;
    const float* B = We + (size_t)e * DDIM * HDIM;

    __shared__ float As[8][128];
    __shared__ float Bs[8][128];
    __shared__ int   sTok[128];
    __shared__ float sGate[128];

    const int tid = threadIdx.x;
    if (tid < 128) {
        int r = m0 + tid;
        if (r < rows) { sTok[tid] = g_tok[base + r]; sGate[tid] = g_gate[base + r]; }
        else          { sTok[tid] = 0;               sGate[tid] = 0.f; }
    }
    __syncthreads();

    const int tx = tid & 15;     // n-direction, 0..15
    const int ty = tid >> 4;     // m-direction, 0..15

    // A gather pointers: thread loads one float4 of x (4 consecutive k)
    const int am = tid >> 1;            // 0..127 (m within tile)
    const int ap = (tid & 1) * 4;       // k sub-offset 0 or 4
    const float* arow = x + (size_t)sTok[am] * DDIM + ap;
    // B pointers: thread loads one float4 (4 consecutive n)
    const int bk = tid >> 5;            // 0..7 (k within tile)
    const int bn = (tid & 31) * 4;      // 0..124
    const float* bptr = B + (size_t)bk * HDIM + n0 + bn;

    unsigned long long acc[8][4];       // 8 m-rows x 4 f32x2 n-pairs
#pragma unroll
    for (int i = 0; i < 8; i++)
#pragma unroll
        for (int p = 0; p < 4; p++) acc[i][p] = 0ull;

    float4 av  = *(const float4*)(arow);
    float4 bv4 = *(const float4*)(bptr);

#pragma unroll 1
    for (int k0 = 0; k0 < DDIM; k0 += 8) {
        __syncthreads();
        As[ap + 0][am] = av.x;
        As[ap + 1][am] = av.y;
        As[ap + 2][am] = av.z;
        As[ap + 3][am] = av.w;
        *(float4*)&Bs[bk][bn] = bv4;
        __syncthreads();

        if (k0 + 8 < DDIM) {
            av  = *(const float4*)(arow + k0 + 8);
            bv4 = *(const float4*)(bptr + (size_t)(k0 + 8) * HDIM);
        }

#pragma unroll
        for (int kk = 0; kk < 8; kk++) {
            float4 A0 = *(const float4*)&As[kk][ty * 4];
            float4 A1 = *(const float4*)&As[kk][64 + ty * 4];
            float4 B0 = *(const float4*)&Bs[kk][tx * 4];
            float4 B1 = *(const float4*)&Bs[kk][64 + tx * 4];
            unsigned long long bp[4];
            bp[0] = pack2(B0.x, B0.y);
            bp[1] = pack2(B0.z, B0.w);
            bp[2] = pack2(B1.x, B1.y);
            bp[3] = pack2(B1.z, B1.w);
            float ar[8] = {A0.x, A0.y, A0.z, A0.w, A1.x, A1.y, A1.z, A1.w};
#pragma unroll
            for (int mi = 0; mi < 8; mi++) {
                unsigned long long ad = pack2(ar[mi], ar[mi]);
#pragma unroll
                for (int p = 0; p < 4; p++) fma2(acc[mi][p], ad, bp[p]);
            }
        }
    }

    // Epilogue: gate * (acc + be) -> atomicAdd into out
    const int c0 = n0 + tx * 4;
    const int c1 = n0 + 64 + tx * 4;
    const float* beE = be + e * HDIM;
    float bv[8];
#pragma unroll
    for (int q = 0; q < 4; q++) { bv[q] = beE[c0 + q]; bv[4 + q] = beE[c1 + q]; }

#pragma unroll
    for (int mi = 0; mi < 8; mi++) {
        int ml = (mi < 4) ? (ty * 4 + mi) : (64 + ty * 4 + (mi - 4));
        int r  = m0 + ml;
        if (r < rows) {
            float g = sGate[ml];
            float* orow = out + (size_t)sTok[ml] * HDIM;
#pragma unroll
            for (int p = 0; p < 4; p++) {
                F2 v; v.u = acc[mi][p];
                int j   = p * 2;
                int col = (j < 4) ? (c0 + j) : (c1 + (j - 4));
                atomicAdd(&orow[col],     g * (v.f[0] + bv[j]));
                atomicAdd(&orow[col + 1], g * (v.f[1] + bv[j + 1]));
            }
        }
    }
}

// ---------------- launch ----------------
extern "C" void kernel_launch(void* const* d_in, const int* in_sizes, int n_in,
                              void* d_out, int out_size) {
    const float* x  = (const float*)d_in[0];   // [T, D]
    const float* Wg = (const float*)d_in[1];   // [D, E]
    const float* We = (const float*)d_in[2];   // [E, D, H]
    const float* be = (const float*)d_in[3];   // [E, H]
    float* out = (float*)d_out;                // [T, H]

    (void)in_sizes; (void)n_in;

    moe_zero_counts<<<1, 32>>>();
    moe_gate<<<T_TOK / 8, 256>>>(x, Wg);
    moe_offsets<<<1, 32>>>();
    moe_scatter<<<NSLOT / 256, 256>>>();
    moe_zero_out<<<out_size / (256 * 4), 256>>>((float4*)out);

    dim3 grid(HDIM / 128, T_TOK / 128, NEXP);  // (8, 64, 8); y covers worst case
    moe_gemm<<<grid, 256>>>(x, We, be, out);
}

// round 14
// speedup vs baseline: 1.0019x; 1.0019x over previous
#include <cuda_runtime.h>
#include <cuda_bf16.h>
#include <math.h>

// Problem constants (fixed by setup_inputs)
#define T_TOK   8192      // B*S = 4*2048
#define DDIM    1024
#define NEXP    8
#define HDIM    1024
#define NSLOT   (2*T_TOK) // top-2 slots

// ---------------- scratch (no allocations allowed) ----------------
__device__ int   g_counts[NEXP];
__device__ int   g_offsets[NEXP];
__device__ int   g_slot_e[NSLOT];
__device__ int   g_slot_pos[NSLOT];
__device__ float g_slot_g[NSLOT];
__device__ int   g_tok[NSLOT];
__device__ float g_gate[NSLOT];

// ---------------- packed fp32x2 helpers (Blackwell FFMA2) ----------------
__device__ __forceinline__ unsigned long long pack2(float x, float y) {
    unsigned long long r;
    asm("mov.b64 %0, {%1, %2};" : "=l"(r) : "f"(x), "f"(y));
    return r;
}
__device__ __forceinline__ void fma2(unsigned long long& d,
                                     unsigned long long a,
                                     unsigned long long b) {
    asm("fma.rn.f32x2 %0, %1, %2, %0;" : "+l"(d) : "l"(a), "l"(b));
}
union F2 { unsigned long long u; float f[2]; };

// ---------------- kernel 0: zero expert counters ----------------
__global__ void moe_zero_counts() {
    if (threadIdx.x < NEXP) g_counts[threadIdx.x] = 0;
}

// ---------------- kernel 1: gating (one warp per token) ----------------
// logits[e] = x[t]·Wg[:,e]; top-2 of logits; renormalized top-2 softmax
// gates == exp(l_i)/(exp(l0)+exp(l1)) (identical to softmax-then-renorm).
__global__ void moe_gate(const float* __restrict__ x,
                         const float* __restrict__ Wg) {
    __shared__ float sWgT[NEXP][DDIM];   // 32 KB, transposed for conflict-free reads
    int tid = threadIdx.x;
    for (int i = tid; i < DDIM * NEXP; i += 256) {
        // Wg is [D, E] row-major: element i -> d = i/8, e = i%8
        sWgT[i & 7][i >> 3] = Wg[i];
    }
    __syncthreads();

    int warp = tid >> 5;
    int lane = tid & 31;
    int t = blockIdx.x * 8 + warp;          // grid = 1024 blocks * 8 warps = 8192

    float acc[NEXP];
#pragma unroll
    for (int e = 0; e < NEXP; e++) acc[e] = 0.f;

    const float* xr = x + (size_t)t * DDIM;
    for (int d = lane; d < DDIM; d += 32) {
        float xv = xr[d];
#pragma unroll
        for (int e = 0; e < NEXP; e++) acc[e] += xv * sWgT[e][d];
    }
#pragma unroll
    for (int e = 0; e < NEXP; e++) {
#pragma unroll
        for (int o = 16; o > 0; o >>= 1)
            acc[e] += __shfl_xor_sync(0xFFFFFFFFu, acc[e], o);
    }

    if (lane == 0) {
        int e0 = 0; float m1 = acc[0];
#pragma unroll
        for (int e = 1; e < NEXP; e++)
            if (acc[e] > m1) { m1 = acc[e]; e0 = e; }
        int e1 = (e0 == 0) ? 1 : 0; float m2 = acc[e1];
#pragma unroll
        for (int e = 0; e < NEXP; e++)
            if (e != e0 && acc[e] > m2) { m2 = acc[e]; e1 = e; }
        float r  = expf(m2 - m1);           // <= 1
        float g0 = 1.f / (1.f + r);
        float g1 = r   / (1.f + r);

        int p0 = atomicAdd(&g_counts[e0], 1);
        int p1 = atomicAdd(&g_counts[e1], 1);
        int s = 2 * t;
        g_slot_e[s]     = e0; g_slot_pos[s]     = p0; g_slot_g[s]     = g0;
        g_slot_e[s + 1] = e1; g_slot_pos[s + 1] = p1; g_slot_g[s + 1] = g1;
    }
}

// ---------------- kernel 2: tiny prefix over 8 experts ----------------
__global__ void moe_offsets() {
    if (threadIdx.x == 0) {
        int s = 0;
#pragma unroll
        for (int e = 0; e < NEXP; e++) { g_offsets[e] = s; s += g_counts[e]; }
    }
}

// ---------------- kernel 3: scatter token lists ----------------
__global__ void moe_scatter() {
    int i = blockIdx.x * 256 + threadIdx.x;     // NSLOT = 16384 threads
    if (i < NSLOT) {
        int e   = g_slot_e[i];
        int loc = g_offsets[e] + g_slot_pos[i];
        g_tok[loc]  = i >> 1;                   // token id
        g_gate[loc] = g_slot_g[i];
    }
}

// ---------------- kernel 4: zero output (out gets 2 atomic adds/elem) ----
__global__ void moe_zero_out(float4* __restrict__ out4) {
    int gid = blockIdx.x * 256 + threadIdx.x;   // out_size/4 threads
    out4[gid] = make_float4(0.f, 0.f, 0.f, 0.f);
}

// ---------------- kernel 5: grouped gather-SGEMM, 128x128x8 tile ----------
// Y[row, h] = gate(row) * ( x[tok(row)] · We[e][:, h] + be[e][h] )
// accumulated into out[tok(row), h] via atomicAdd (exactly 2 adds/elem ->
// commutative -> deterministic).
__global__ void __launch_bounds__(256, 2)
moe_gemm(const float* __restrict__ x,
         const float* __restrict__ We,
         const float* __restrict__ be,
         float* __restrict__ out) {
    const int e    = blockIdx.z;
    const int rows = g_counts[e];
    const int m0   = blockIdx.y * 128;
    if (m0 >= rows) return;
    const int base = g_offsets[e];
    const int n0   = blockIdx.x * 128;
    const float* B = We + (size_t)e * DDIM * HDIM;

    __shared__ float As[8][128];
    __shared__ float Bs[8][128];
    __shared__ int   sTok[128];
    __shared__ float sGate[128];

    const int tid = threadIdx.x;
    if (tid < 128) {
        int r = m0 + tid;
        if (r < rows) { sTok[tid] = g_tok[base + r]; sGate[tid] = g_gate[base + r]; }
        else          { sTok[tid] = 0;               sGate[tid] = 0.f; }
    }
    __syncthreads();

    const int tx = tid & 15;     // n-direction, 0..15
    const int ty = tid >> 4;     // m-direction, 0..15

    // A gather pointers: thread loads one float4 of x (4 consecutive k)
    const int am = tid >> 1;            // 0..127 (m within tile)
    const int ap = (tid & 1) * 4;       // k sub-offset 0 or 4
    const float* arow = x + (size_t)sTok[am] * DDIM + ap;
    // B pointers: thread loads one float4 (4 consecutive n)
    const int bk = tid >> 5;            // 0..7 (k within tile)
    const int bn = (tid & 31) * 4;      // 0..124
    const float* bptr = B + (size_t)bk * HDIM + n0 + bn;

    unsigned long long acc[8][4];       // 8 m-rows x 4 f32x2 n-pairs
#pragma unroll
    for (int i = 0; i < 8; i++)
#pragma unroll
        for (int p = 0; p < 4; p++) acc[i][p] = 0ull;

    float4 av  = *(const float4*)(arow);
    float4 bv4 = *(const float4*)(bptr);

#pragma unroll 1
    for (int k0 = 0; k0 < DDIM; k0 += 8) {
        __syncthreads();
        As[ap + 0][am] = av.x;
        As[ap + 1][am] = av.y;
        As[ap + 2][am] = av.z;
        As[ap + 3][am] = av.w;
        *(float4*)&Bs[bk][bn] = bv4;
        __syncthreads();

        if (k0 + 8 < DDIM) {
            av  = *(const float4*)(arow + k0 + 8);
            bv4 = *(const float4*)(bptr + (size_t)(k0 + 8) * HDIM);
        }

#pragma unroll
        for (int kk = 0; kk < 8; kk++) {
            float4 A0 = *(const float4*)&As[kk][ty * 4];
            float4 A1 = *(const float4*)&As[kk][64 + ty * 4];
            float4 B0 = *(const float4*)&Bs[kk][tx * 4];
            float4 B1 = *(const float4*)&Bs[kk][64 + tx * 4];
            unsigned long long bp[4];
            bp[0] = pack2(B0.x, B0.y);
            bp[1] = pack2(B0.z, B0.w);
            bp[2] = pack2(B1.x, B1.y);
            bp[3] = pack2(B1.z, B1.w);
            float ar[8] = {A0.x, A0.y, A0.z, A0.w, A1.x, A1.y, A1.z, A1.w};
#pragma unroll
            for (int mi = 0; mi < 8; mi++) {
                unsigned long long ad = pack2(ar[mi], ar[mi]);
#pragma unroll
                for (int p = 0; p < 4; p++) fma2(acc[mi][p], ad, bp[p]);
            }
        }
    }

    // Epilogue: gate * (acc + be) -> atomicAdd into out
    const int c0 = n0 + tx * 4;
    const int c1 = n0 + 64 + tx * 4;
    const float* beE = be + e * HDIM;
    float bv[8];
#pragma unroll
    for (int q = 0; q < 4; q++) { bv[q] = beE[c0 + q]; bv[4 + q] = beE[c1 + q]; }

#pragma unroll
    for (int mi = 0; mi < 8; mi++) {
        int ml = (mi < 4) ? (ty * 4 + mi) : (64 + ty * 4 + (mi - 4));
        int r  = m0 + ml;
        if (r < rows) {
            float g = sGate[ml];
            float* orow = out + (size_t)sTok[ml] * HDIM;
#pragma unroll
            for (int p = 0; p < 4; p++) {
                F2 v; v.u = acc[mi][p];
                int j   = p * 2;
                int col = (j < 4) ? (c0 + j) : (c1 + (j - 4));
                atomicAdd(&orow[col],     g * (v.f[0] + bv[j]));
                atomicAdd(&orow[col + 1], g * (v.f[1] + bv[j + 1]));
            }
        }
    }
}

// ---------------- launch ----------------
extern "C" void kernel_launch(void* const* d_in, const int* in_sizes, int n_in,
                              void* d_out, int out_size) {
    const float* x  = (const float*)d_in[0];   // [T, D]
    const float* Wg = (const float*)d_in[1];   // [D, E]
    const float* We = (const float*)d_in[2];   // [E, D, H]
    const float* be = (const float*)d_in[3];   // [E, H]
    float* out = (float*)d_out;                // [T, H]

    (void)in_sizes; (void)n_in;

    moe_zero_counts<<<1, 32>>>();
    moe_gate<<<T_TOK / 8, 256>>>(x, Wg);
    moe_offsets<<<1, 32>>>();
    moe_scatter<<<NSLOT / 256, 256>>>();
    moe_zero_out<<<out_size / (256 * 4), 256>>>((float4*)out);

    dim3 grid(HDIM / 128, T_TOK / 128, NEXP);  // (8, 64, 8); y covers worst case
    moe_gemm<<<grid, 256>>>(x, We, be, out);
}